// round 7
// baseline (speedup 1.0000x reference)
#include <cuda_runtime.h>
#include <cuda_bf16.h>
#include <math.h>

// ---------------------------------------------------------------------------
// ContrastiveEnergyLearning — Round 7: 2-term bf16 split MMA (Xh*Wh + Xh*Wl),
// 128-row CTAs / 512 threads (4 warps per SMSP), exact-fp32 near-tie fixup.
// Launch order puts energyT at slot #4 so ncu captures it.
// ---------------------------------------------------------------------------

#define NB 32768
#define RTOT (NB * 17)             // 557056
#define NBLK (RTOT / 128)          // 4352
#define TEMP_INV (1.0f / 0.07f)

__device__ float g_A[NB * 256];    // anchor @ W1x^T + b1 (2-term bf16 MMA)
__device__ float g_energy[RTOT];
__device__ float g_part[128][4];

// prepped bf16 hi/lo weights, chunked [chunk][out][72] (pitch 144B)
__device__ unsigned char g_W1xh[147456], g_W1xl[147456];
__device__ unsigned char g_W1yh[147456], g_W1yl[147456];
__device__ unsigned char g_W2h[73728],   g_W2l[73728];
__device__ unsigned char g_W3h[17408],   g_W3l[17408];   // full-K pitch 136

typedef unsigned int u32;

__device__ __forceinline__ float gelu_exact(float x) {
    return 0.5f * x * (1.0f + erff(x * 0.7071067811865476f));
}
__device__ __forceinline__ u32 bfpair(float a, float b) {
    __nv_bfloat162 t = __floats2bfloat162_rn(a, b);
    return *(u32*)&t;
}
__device__ __forceinline__ u32 smem_u32(const void* p) {
    u32 a;
    asm("{ .reg .u64 t; cvta.to.shared.u64 t, %1; cvt.u32.u64 %0, t; }"
        : "=r"(a) : "l"(p));
    return a;
}
__device__ __forceinline__ void ldsm4(u32& r0, u32& r1, u32& r2, u32& r3, u32 a) {
    asm volatile("ldmatrix.sync.aligned.m8n8.x4.shared.b16 {%0,%1,%2,%3},[%4];"
                 : "=r"(r0), "=r"(r1), "=r"(r2), "=r"(r3) : "r"(a));
}
__device__ __forceinline__ void mma_bf16(float d[4], u32 a0, u32 a1, u32 a2, u32 a3,
                                         u32 b0, u32 b1) {
    asm volatile("mma.sync.aligned.m16n8k16.row.col.f32.bf16.bf16.f32 "
                 "{%0,%1,%2,%3},{%4,%5,%6,%7},{%8,%9},{%0,%1,%2,%3};"
                 : "+f"(d[0]), "+f"(d[1]), "+f"(d[2]), "+f"(d[3])
                 : "r"(a0), "r"(a1), "r"(a2), "r"(a3), "r"(b0), "r"(b1));
}

// ---------------- SMEM layout (bytes), energyT ------------------------------
// region A [0, 69632): XH (128 x 528B) then reused as H2h (128x272) + H3 (128x272)
// region B [69632, 137216): H1h (128 x 528B); later W4 (256B)
// region C [137216, 210944): WH (36864) + WL (36864)
#define XH_OFF   0u
#define H2H_OFF  0u
#define H3_OFF   34816u
#define H1H_OFF  69632u
#define W4_OFF   69632u
#define WH_OFF   137216u
#define WL_OFF   174080u
#define SMEM_EN  210944
#define SMEM_A   143360          // mmaA: XH 67584 @0, WH @69632, WL @106496
#define AWH_OFF  69632u
#define AWL_OFF  106496u

// ---------------------------------------------------------------------------
// prep kernels (two, for launch-slot alignment)
// ---------------------------------------------------------------------------
__global__ void prepW_a(const float* __restrict__ W1) {
    int i = blockIdx.x * 256 + threadIdx.x;          // 131072 items
    if (i >= 131072) return;
    int half = i >> 16;
    int j = i & 65535;
    int o = j >> 8, k = j & 255;
    float w = W1[o * 512 + half * 256 + k];
    u32 off = (((u32)(k >> 6) * 256 + o) * 72 + (k & 63)) * 2;
    __nv_bfloat16 h = __float2bfloat16_rn(w);
    __nv_bfloat16 l = __float2bfloat16_rn(w - __bfloat162float(h));
    unsigned char* dh = half ? g_W1yh : g_W1xh;
    unsigned char* dl = half ? g_W1yl : g_W1xl;
    *(__nv_bfloat16*)(dh + off) = h;
    *(__nv_bfloat16*)(dl + off) = l;
}

__global__ void prepW_b(const float* __restrict__ W2, const float* __restrict__ W3) {
    int i = blockIdx.x * 256 + threadIdx.x;          // 40960 items
    float w; unsigned char *dh, *dl; u32 off;
    if (i < 32768) {
        int o = i >> 8, k = i & 255;
        w = W2[o * 256 + k];
        off = (((u32)(k >> 6) * 128 + o) * 72 + (k & 63)) * 2;
        dh = g_W2h; dl = g_W2l;
    } else if (i < 40960) {
        int j = i - 32768;
        int o = j >> 7, k = j & 127;
        w = W3[o * 128 + k];
        off = ((u32)o * 136 + k) * 2;
        dh = g_W3h; dl = g_W3l;
    } else return;
    __nv_bfloat16 h = __float2bfloat16_rn(w);
    __nv_bfloat16 l = __float2bfloat16_rn(w - __bfloat162float(h));
    *(__nv_bfloat16*)(dh + off) = h;
    *(__nv_bfloat16*)(dl + off) = l;
}

// ---------------- staging helpers -------------------------------------------
__device__ __forceinline__ void stage_w(char* smc, u32 hoff, u32 loff,
                                        const unsigned char* gh, const unsigned char* gl,
                                        int bytes, int tid, int nthr) {
    const uint4* sh = (const uint4*)gh;
    const uint4* sl = (const uint4*)gl;
    uint4* dh = (uint4*)(smc + hoff);
    uint4* dl = (uint4*)(smc + loff);
    for (int i = tid; i < (bytes >> 4); i += nthr) { dh[i] = sh[i]; dl[i] = sl[i]; }
}

// one K=16 MMA step, 2 split terms. A: hi only. B: hi(lanes<16)/lo via x4 trick.
template <int NT, int WP, int AP>
__device__ __forceinline__ void kstep(u32 sb, u32 aoff, int kgA, int kB, int nbase,
                                      int arow, int akof, int bl8, int bk8, u32 bsel,
                                      float acc[2][NT][4]) {
    u32 ah[2][4];
    #pragma unroll
    for (int mt = 0; mt < 2; mt++) {
        u32 ao = aoff + (u32)(arow + mt * 16) * AP + (u32)(kgA + akof) * 2;
        ldsm4(ah[mt][0], ah[mt][1], ah[mt][2], ah[mt][3], sb + ao);
    }
    #pragma unroll
    for (int nt = 0; nt < NT; nt++) {
        u32 b0, b1, b2, b3;
        ldsm4(b0, b1, b2, b3, bsel + (u32)(kB + bk8) * 2 + (u32)(nbase + nt * 8 + bl8) * WP);
        #pragma unroll
        for (int mt = 0; mt < 2; mt++) {
            mma_bf16(acc[mt][nt], ah[mt][0], ah[mt][1], ah[mt][2], ah[mt][3], b0, b1);
            mma_bf16(acc[mt][nt], ah[mt][0], ah[mt][1], ah[mt][2], ah[mt][3], b2, b3);
        }
    }
}

// ---------------------------------------------------------------------------
// mmaA: g_A = anchor @ W1x^T + b1 (128 rows/CTA, 512 threads)
// ---------------------------------------------------------------------------
__global__ void __launch_bounds__(512, 1)
mmaA(const float* __restrict__ anchor, const float* __restrict__ b1) {
    extern __shared__ char smc[];
    const u32 sb = smem_u32(smc);
    const int tid = threadIdx.x, lane = tid & 31, wid = tid >> 5;
    const int r0 = blockIdx.x * 128;
    const int mbase = (wid >> 2) * 32;
    const int nbase = (wid & 3) * 64;
    const int arow = mbase + (lane & 15);
    const int akof = (lane & 16) ? 8 : 0;
    const int bl8 = lane & 7, bk8 = lane & 8;
    const u32 bsel = (lane < 16) ? (sb + AWH_OFF) : (sb + AWL_OFF);

    for (int i = tid; i < 128 * 64; i += 512) {
        int row = i >> 6, q = i & 63;
        float4 v = ((const float4*)(anchor + (size_t)(r0 + row) * 256))[q];
        uint2 hh = {bfpair(v.x, v.y), bfpair(v.z, v.w)};
        *(uint2*)(smc + XH_OFF + (u32)row * 528 + q * 8) = hh;
    }
    stage_w(smc, AWH_OFF, AWL_OFF, g_W1xh, g_W1xl, 36864, tid, 512);
    __syncthreads();

    float acc[2][8][4];
    #pragma unroll
    for (int mt = 0; mt < 2; mt++)
        #pragma unroll
        for (int nt = 0; nt < 8; nt++)
            #pragma unroll
            for (int q = 0; q < 4; q++) acc[mt][nt][q] = 0.f;

    for (int c = 0; c < 4; c++) {
        #pragma unroll
        for (int ks = 0; ks < 4; ks++)
            kstep<8, 144, 528>(sb, XH_OFF, c * 64 + ks * 16, ks * 16, nbase,
                               arow, akof, bl8, bk8, bsel, acc);
        __syncthreads();
        if (c < 3) {
            stage_w(smc, AWH_OFF, AWL_OFF, g_W1xh + (c + 1) * 36864,
                    g_W1xl + (c + 1) * 36864, 36864, tid, 512);
            __syncthreads();
        }
    }

    const int row0 = mbase + (lane >> 2);
    const int col0 = nbase + (lane & 3) * 2;
    #pragma unroll
    for (int mt = 0; mt < 2; mt++)
        #pragma unroll
        for (int nt = 0; nt < 8; nt++) {
            int col = col0 + nt * 8;
            float2 bb = *(const float2*)(b1 + col);
            #pragma unroll
            for (int h = 0; h < 2; h++) {
                int rr = row0 + mt * 16 + h * 8;
                float2 v = {acc[mt][nt][2 * h] + bb.x, acc[mt][nt][2 * h + 1] + bb.y};
                *(float2*)(g_A + (size_t)(r0 + rr) * 256 + col) = v;
            }
        }
}

// ---------------------------------------------------------------------------
// energyT: fused 4-layer MLP, 128 rows/CTA, 512 threads
// ---------------------------------------------------------------------------
__global__ void __launch_bounds__(512, 1)
energyT(const float* __restrict__ positive, const float* __restrict__ negatives,
        const float* __restrict__ b2, const float* __restrict__ b3,
        const float* __restrict__ W4, const float* __restrict__ b4) {
    extern __shared__ char smc[];
    const u32 sb = smem_u32(smc);
    const int tid = threadIdx.x, lane = tid & 31, wid = tid >> 5;
    const int r0 = blockIdx.x * 128;
    const int mbase = (wid >> 2) * 32;
    const int nb = wid & 3;
    const int row0 = mbase + (lane >> 2);
    const int col0 = (lane & 3) * 2;
    const int arow = mbase + (lane & 15);
    const int akof = (lane & 16) ? 8 : 0;
    const int bl8 = lane & 7, bk8 = lane & 8;
    const u32 bsel = (lane < 16) ? (sb + WH_OFF) : (sb + WL_OFF);

    // ---- stage Y tile (hi only) + W1y chunk 0
    for (int i = tid; i < 128 * 64; i += 512) {
        int row = i >> 6, q = i & 63;
        int g = r0 + row, b = g / 17, j = g - b * 17;
        const float* src = j ? negatives + ((size_t)(b * 16 + j - 1)) * 256
                             : positive + (size_t)b * 256;
        float4 v = ((const float4*)src)[q];
        uint2 hh = {bfpair(v.x, v.y), bfpair(v.z, v.w)};
        *(uint2*)(smc + XH_OFF + (u32)row * 528 + q * 8) = hh;
    }
    stage_w(smc, WH_OFF, WL_OFF, g_W1yh, g_W1yl, 36864, tid, 512);
    __syncthreads();

    // ================= Layer 1: 128x256, K=256 ==============================
    {
        const int nbase = nb * 64;
        float acc[2][8][4];
        #pragma unroll
        for (int mt = 0; mt < 2; mt++)
            #pragma unroll
            for (int nt = 0; nt < 8; nt++)
                #pragma unroll
                for (int q = 0; q < 4; q++) acc[mt][nt][q] = 0.f;

        for (int c = 0; c < 4; c++) {
            #pragma unroll
            for (int ks = 0; ks < 4; ks++)
                kstep<8, 144, 528>(sb, XH_OFF, c * 64 + ks * 16, ks * 16, nbase,
                                   arow, akof, bl8, bk8, bsel, acc);
            __syncthreads();
            if (c < 3) {
                stage_w(smc, WH_OFF, WL_OFF, g_W1yh + (c + 1) * 36864,
                        g_W1yl + (c + 1) * 36864, 36864, tid, 512);
                __syncthreads();
            }
        }
        // epilogue: + g_A, GELU -> H1h (bf16 hi only)
        #pragma unroll
        for (int mt = 0; mt < 2; mt++)
            #pragma unroll
            for (int nt = 0; nt < 8; nt++) {
                int col = nbase + nt * 8 + col0;
                #pragma unroll
                for (int h = 0; h < 2; h++) {
                    int rr = row0 + mt * 16 + h * 8;
                    int gb = (r0 + rr) / 17;
                    float2 a = *(const float2*)(g_A + (size_t)gb * 256 + col);
                    float v0 = gelu_exact(acc[mt][nt][2 * h] + a.x);
                    float v1 = gelu_exact(acc[mt][nt][2 * h + 1] + a.y);
                    *(u32*)(smc + H1H_OFF + (u32)rr * 528 + col * 2) = bfpair(v0, v1);
                }
            }
    }
    stage_w(smc, WH_OFF, WL_OFF, g_W2h, g_W2l, 18432, tid, 512);
    __syncthreads();

    // ================= Layer 2: 128x128, K=256 ==============================
    {
        const int nbase = nb * 32;
        float acc[2][4][4];
        #pragma unroll
        for (int mt = 0; mt < 2; mt++)
            #pragma unroll
            for (int nt = 0; nt < 4; nt++)
                #pragma unroll
                for (int q = 0; q < 4; q++) acc[mt][nt][q] = 0.f;

        for (int c = 0; c < 4; c++) {
            #pragma unroll
            for (int ks = 0; ks < 4; ks++)
                kstep<4, 144, 528>(sb, H1H_OFF, c * 64 + ks * 16, ks * 16, nbase,
                                   arow, akof, bl8, bk8, bsel, acc);
            __syncthreads();
            if (c < 3) {
                stage_w(smc, WH_OFF, WL_OFF, g_W2h + (c + 1) * 18432,
                        g_W2l + (c + 1) * 18432, 18432, tid, 512);
                __syncthreads();
            }
        }
        // epilogue -> H2h (region A; X dead)
        #pragma unroll
        for (int mt = 0; mt < 2; mt++)
            #pragma unroll
            for (int nt = 0; nt < 4; nt++) {
                int col = nbase + nt * 8 + col0;
                float2 bb = *(const float2*)(b2 + col);
                #pragma unroll
                for (int h = 0; h < 2; h++) {
                    int rr = row0 + mt * 16 + h * 8;
                    float v0 = gelu_exact(acc[mt][nt][2 * h] + bb.x);
                    float v1 = gelu_exact(acc[mt][nt][2 * h + 1] + bb.y);
                    *(u32*)(smc + H2H_OFF + (u32)rr * 272 + col * 2) = bfpair(v0, v1);
                }
            }
    }
    // stage W3 (W region) + W4 (H1 region, both free now)
    stage_w(smc, WH_OFF, WL_OFF, g_W3h, g_W3l, 17408, tid, 512);
    if (tid < 64) ((float*)(smc + W4_OFF))[tid] = W4[tid];
    __syncthreads();

    // ================= Layer 3: 128x64, K=128 ===============================
    {
        const int nbase = nb * 16;
        float acc[2][2][4];
        #pragma unroll
        for (int mt = 0; mt < 2; mt++)
            #pragma unroll
            for (int nt = 0; nt < 2; nt++)
                #pragma unroll
                for (int q = 0; q < 4; q++) acc[mt][nt][q] = 0.f;

        #pragma unroll
        for (int ks = 0; ks < 8; ks++)
            kstep<2, 272, 272>(sb, H2H_OFF, ks * 16, ks * 16, nbase,
                               arow, akof, bl8, bk8, bsel, acc);

        // epilogue -> H3 fp32 (disjoint from H2h)
        float* H3 = (float*)(smc + H3_OFF);
        #pragma unroll
        for (int mt = 0; mt < 2; mt++)
            #pragma unroll
            for (int nt = 0; nt < 2; nt++) {
                int col = nbase + nt * 8 + col0;
                float2 bb = *(const float2*)(b3 + col);
                #pragma unroll
                for (int h = 0; h < 2; h++) {
                    int rr = row0 + mt * 16 + h * 8;
                    float2 v = {gelu_exact(acc[mt][nt][2 * h] + bb.x),
                                gelu_exact(acc[mt][nt][2 * h + 1] + bb.y)};
                    *(float2*)(H3 + rr * 68 + col) = v;
                }
            }
    }
    __syncthreads();

    // ================= Layer 4: dot(64) =====================================
    if (tid < 128) {
        const float* H3 = (const float*)(smc + H3_OFF);
        const float* w4 = (const float*)(smc + W4_OFF);
        float e = b4[0];
        #pragma unroll
        for (int k = 0; k < 64; k++) e += H3[tid * 68 + k] * w4[k];
        g_energy[r0 + tid] = e;
    }
}

// ---------------------------------------------------------------------------
// fixup: exact fp32 recompute of flagged (near-tie) batches
// ---------------------------------------------------------------------------
__global__ void __launch_bounds__(128)
fixup(const float* __restrict__ anchor, const float* __restrict__ positive,
      const float* __restrict__ negatives,
      const float* __restrict__ W1, const float* __restrict__ b1,
      const float* __restrict__ W2, const float* __restrict__ b2,
      const float* __restrict__ W3, const float* __restrict__ b3,
      const float* __restrict__ W4, const float* __restrict__ b4) {
    const int b = blockIdx.x, tid = threadIdx.x;
    __shared__ float apart[256], ys[256], h1[256], h2[128], red[128];
    __shared__ int flag;

    if (tid == 0) {
        const float* e = &g_energy[(size_t)b * 17];
        float mn = e[1];
        #pragma unroll
        for (int j = 2; j < 17; j++) mn = fminf(mn, e[j]);
        flag = fabsf(e[0] - mn) < 0.015f;
    }
    __syncthreads();
    if (!flag) return;

    ys[tid] = anchor[(size_t)b * 256 + tid];
    ys[tid + 128] = anchor[(size_t)b * 256 + 128 + tid];
    __syncthreads();
    #pragma unroll
    for (int h = 0; h < 2; h++) {
        int o = tid + h * 128;
        float acc = b1[o];
        const float* w = W1 + (size_t)o * 512;
        for (int k = 0; k < 256; k++) acc += w[k] * ys[k];
        apart[o] = acc;
    }
    __syncthreads();

    for (int j = 0; j < 17; j++) {
        const float* src = j ? negatives + ((size_t)(b * 16 + j - 1)) * 256
                             : positive + (size_t)b * 256;
        ys[tid] = src[tid];
        ys[tid + 128] = src[tid + 128];
        __syncthreads();
        #pragma unroll
        for (int h = 0; h < 2; h++) {
            int o = tid + h * 128;
            float acc = apart[o];
            const float* w = W1 + (size_t)o * 512 + 256;
            for (int k = 0; k < 256; k++) acc += w[k] * ys[k];
            h1[o] = gelu_exact(acc);
        }
        __syncthreads();
        {
            float acc = b2[tid];
            const float* w = W2 + (size_t)tid * 256;
            for (int k = 0; k < 256; k++) acc += w[k] * h1[k];
            h2[tid] = gelu_exact(acc);
        }
        __syncthreads();
        if (tid < 64) {
            float acc = b3[tid];
            const float* w = W3 + (size_t)tid * 128;
            for (int k = 0; k < 128; k++) acc += w[k] * h2[k];
            red[tid] = gelu_exact(acc) * W4[tid];
        } else red[tid] = 0.f;
        __syncthreads();
        for (int st = 32; st > 0; st >>= 1) {
            if (tid < st) red[tid] += red[tid + st];
            __syncthreads();
        }
        if (tid == 0) g_energy[(size_t)b * 17 + j] = red[0] + b4[0];
        __syncthreads();
    }
}

// ---------------------------------------------------------------------------
// reductions (deterministic, unchanged)
// ---------------------------------------------------------------------------
__global__ void reduce1() {
    __shared__ float sl[256], sp[256], sn[256], sa[256];
    const int t = threadIdx.x;
    const int b = blockIdx.x * 256 + t;
    const float* e = &g_energy[(size_t)b * 17];

    float v[17];
    #pragma unroll
    for (int j = 0; j < 17; j++) v[j] = e[j];

    float l0 = -v[0] * TEMP_INV;
    float mx = l0;
    #pragma unroll
    for (int j = 1; j < 17; j++) mx = fmaxf(mx, -v[j] * TEMP_INV);
    float s = 0.f;
    #pragma unroll
    for (int j = 0; j < 17; j++) s += expf(-v[j] * TEMP_INV - mx);
    float loss = mx + logf(s) - l0;

    float pos = v[0], neg = 0.f, ok = 1.f;
    #pragma unroll
    for (int j = 1; j < 17; j++) {
        neg += v[j];
        if (v[j] < v[0]) ok = 0.f;
    }

    sl[t] = loss; sp[t] = pos; sn[t] = neg; sa[t] = ok;
    __syncthreads();
    for (int st = 128; st > 0; st >>= 1) {
        if (t < st) {
            sl[t] += sl[t + st]; sp[t] += sp[t + st];
            sn[t] += sn[t + st]; sa[t] += sa[t + st];
        }
        __syncthreads();
    }
    if (t == 0) {
        g_part[blockIdx.x][0] = sl[0];
        g_part[blockIdx.x][1] = sp[0];
        g_part[blockIdx.x][2] = sn[0];
        g_part[blockIdx.x][3] = sa[0];
    }
}

__global__ void reduce2(float* __restrict__ out) {
    __shared__ float s[128][4];
    const int t = threadIdx.x;
    #pragma unroll
    for (int c = 0; c < 4; c++) s[t][c] = g_part[t][c];
    __syncthreads();
    for (int st = 64; st > 0; st >>= 1) {
        if (t < st) {
            #pragma unroll
            for (int c = 0; c < 4; c++) s[t][c] += s[t + st][c];
        }
        __syncthreads();
    }
    if (t == 0) {
        out[0] = s[0][0] / 32768.0f;
        out[1] = s[0][1] / 32768.0f;
        out[2] = s[0][2] / (32768.0f * 16.0f);
        out[3] = s[0][3] / 32768.0f;
    }
}

// ---------------------------------------------------------------------------
extern "C" void kernel_launch(void* const* d_in, const int* in_sizes, int n_in,
                              void* d_out, int out_size) {
    const float* anchor    = (const float*)d_in[0];
    const float* positive  = (const float*)d_in[1];
    const float* negatives = (const float*)d_in[2];
    const float* W1 = (const float*)d_in[3];
    const float* b1 = (const float*)d_in[4];
    const float* W2 = (const float*)d_in[5];
    const float* b2 = (const float*)d_in[6];
    const float* W3 = (const float*)d_in[7];
    const float* b3 = (const float*)d_in[8];
    const float* W4 = (const float*)d_in[9];
    const float* b4 = (const float*)d_in[10];
    float* out = (float*)d_out;

    cudaFuncSetAttribute(mmaA,    cudaFuncAttributeMaxDynamicSharedMemorySize, SMEM_A);
    cudaFuncSetAttribute(energyT, cudaFuncAttributeMaxDynamicSharedMemorySize, SMEM_EN);

    prepW_a<<<512, 256>>>(W1);                                     // launch 1
    prepW_b<<<160, 256>>>(W2, W3);                                 // launch 2
    mmaA<<<NB / 128, 512, SMEM_A>>>(anchor, b1);                   // launch 3
    energyT<<<NBLK, 512, SMEM_EN>>>(positive, negatives, b2, b3, W4, b4); // launch 4 (profiled)
    fixup<<<NB, 128>>>(anchor, positive, negatives, W1, b1, W2, b2, W3, b3, W4, b4);
    reduce1<<<128, 256>>>();
    reduce2<<<1, 128>>>(out);
}

// round 8
// speedup vs baseline: 29.8483x; 29.8483x over previous
#include <cuda_runtime.h>
#include <cuda_bf16.h>
#include <math.h>

// ---------------------------------------------------------------------------
// ContrastiveEnergyLearning — Round 8: R6 tensor-core energies (3-term bf16
// split, 64-row/256-thread CTAs: no reg-cap spills) + parallel compact-list
// exact-fp32 fixup (flagK + fixup2) replacing the serial per-batch fixup.
// ---------------------------------------------------------------------------

#define NB 32768
#define RTOT (NB * 17)            // 557056
#define NBLK (RTOT / 64)          // 8704
#define TEMP_INV (1.0f / 0.07f)
#define FIX_THRESH 5e-4f
#define FIXGRID 2048

__device__ float g_A[NB * 256];   // anchor @ W1x^T + b1 (bf16-split MMA)
__device__ float g_energy[RTOT];
__device__ float g_part[128][4];
__device__ int   g_cnt;
__device__ int   g_list[NB];

// prepped bf16 hi/lo weights, chunked [chunk][out][72] (pitch 144B)
__device__ unsigned char g_W1xh[147456], g_W1xl[147456];
__device__ unsigned char g_W1yh[147456], g_W1yl[147456];
__device__ unsigned char g_W2h[73728],   g_W2l[73728];
__device__ unsigned char g_W3h[17408],   g_W3l[17408];   // full-K pitch 136

typedef unsigned int u32;

// ---------------- helpers ---------------------------------------------------
__device__ __forceinline__ float gelu_exact(float x) {
    return 0.5f * x * (1.0f + erff(x * 0.7071067811865476f));
}
__device__ __forceinline__ u32 bfpair(float a, float b) {
    __nv_bfloat162 t = __floats2bfloat162_rn(a, b);
    return *(u32*)&t;
}
__device__ __forceinline__ float bfhi(float a) {
    return __bfloat162float(__float2bfloat16_rn(a));
}
__device__ __forceinline__ u32 smem_u32(const void* p) {
    u32 a;
    asm("{ .reg .u64 t; cvta.to.shared.u64 t, %1; cvt.u32.u64 %0, t; }"
        : "=r"(a) : "l"(p));
    return a;
}
__device__ __forceinline__ void ldsm4(u32& r0, u32& r1, u32& r2, u32& r3, u32 a) {
    asm volatile("ldmatrix.sync.aligned.m8n8.x4.shared.b16 {%0,%1,%2,%3},[%4];"
                 : "=r"(r0), "=r"(r1), "=r"(r2), "=r"(r3) : "r"(a));
}
__device__ __forceinline__ void mma_bf16(float d[4], u32 a0, u32 a1, u32 a2, u32 a3,
                                         u32 b0, u32 b1) {
    asm volatile("mma.sync.aligned.m16n8k16.row.col.f32.bf16.bf16.f32 "
                 "{%0,%1,%2,%3},{%4,%5,%6,%7},{%8,%9},{%0,%1,%2,%3};"
                 : "+f"(d[0]), "+f"(d[1]), "+f"(d[2]), "+f"(d[3])
                 : "r"(a0), "r"(a1), "r"(a2), "r"(a3), "r"(b0), "r"(b1));
}

// ---------------- SMEM layout (bytes) ---------------------------------------
#define XH_OFF   0u        // 64 x 264 bf16 (pitch 528B)
#define XL_OFF   34816u
#define WH_OFF   69632u    // up to 256 x 72 bf16 (pitch 144B)
#define WL_OFF   106496u
#define H1H_OFF  143360u   // 64 x 264 bf16
#define H1L_OFF  177152u
#define H2H_OFF  0u        // 64 x 136 bf16 (pitch 272B) — reuses X region
#define H2L_OFF  17408u
#define H3_OFF   34816u    // 64 x 68 f32 (pitch 272B)
#define W4_OFF   52224u    // 64 f32
#define SMEM_EN  210944
#define SMEM_A   143360

// ---------------------------------------------------------------------------
// prep kernels (also zero the fixup counter each graph replay)
// ---------------------------------------------------------------------------
__global__ void prepW_a(const float* __restrict__ W1) {
    int i = blockIdx.x * 256 + threadIdx.x;          // 131072 items
    if (i == 0) g_cnt = 0;
    if (i >= 131072) return;
    int half = i >> 16;
    int j = i & 65535;
    int o = j >> 8, k = j & 255;
    float w = W1[o * 512 + half * 256 + k];
    u32 off = (((u32)(k >> 6) * 256 + o) * 72 + (k & 63)) * 2;
    __nv_bfloat16 h = __float2bfloat16_rn(w);
    __nv_bfloat16 l = __float2bfloat16_rn(w - __bfloat162float(h));
    unsigned char* dh = half ? g_W1yh : g_W1xh;
    unsigned char* dl = half ? g_W1yl : g_W1xl;
    *(__nv_bfloat16*)(dh + off) = h;
    *(__nv_bfloat16*)(dl + off) = l;
}

__global__ void prepW_b(const float* __restrict__ W2, const float* __restrict__ W3) {
    int i = blockIdx.x * 256 + threadIdx.x;          // 40960 items
    float w; unsigned char *dh, *dl; u32 off;
    if (i < 32768) {
        int o = i >> 8, k = i & 255;
        w = W2[o * 256 + k];
        off = (((u32)(k >> 6) * 128 + o) * 72 + (k & 63)) * 2;
        dh = g_W2h; dl = g_W2l;
    } else if (i < 40960) {
        int j = i - 32768;
        int o = j >> 7, k = j & 127;
        w = W3[o * 128 + k];
        off = ((u32)o * 136 + k) * 2;
        dh = g_W3h; dl = g_W3l;
    } else return;
    __nv_bfloat16 h = __float2bfloat16_rn(w);
    __nv_bfloat16 l = __float2bfloat16_rn(w - __bfloat162float(h));
    *(__nv_bfloat16*)(dh + off) = h;
    *(__nv_bfloat16*)(dl + off) = l;
}

// ---------------- staging helpers --------------------------------------------
__device__ __forceinline__ void stage_w(char* smc, const unsigned char* gh,
                                        const unsigned char* gl, int bytes, int tid) {
    const uint4* sh = (const uint4*)gh;
    const uint4* sl = (const uint4*)gl;
    uint4* dh = (uint4*)(smc + WH_OFF);
    uint4* dl = (uint4*)(smc + WL_OFF);
    for (int i = tid; i < (bytes >> 4); i += 256) { dh[i] = sh[i]; dl[i] = sl[i]; }
}
__device__ __forceinline__ void split_store(char* smc, u32 off, float4 v) {
    uint2 hh, ll;
    hh.x = bfpair(v.x, v.y); hh.y = bfpair(v.z, v.w);
    ll.x = bfpair(v.x - bfhi(v.x), v.y - bfhi(v.y));
    ll.y = bfpair(v.z - bfhi(v.z), v.w - bfhi(v.w));
    *(uint2*)(smc + XH_OFF + off) = hh;
    *(uint2*)(smc + XL_OFF + off) = ll;
}

// one K=16 step of the 256-out tile (2 m-tiles x 8 n-tiles), 3 split terms
__device__ __forceinline__ void l1_kstep(u32 sb, int kg, int kl, int mbase, int nbase,
                                         int lane, float acc[2][8][4]) {
    const int arow = mbase + (lane & 15);
    const int akof = (lane & 16) ? 8 : 0;
    const int bl8 = lane & 7;
    const int bk8 = lane & 8;
    const u32 bbase = ((lane < 16) ? (sb + WH_OFF) : (sb + WL_OFF)) + (u32)(kl + bk8) * 2;
    u32 ah[2][4], al[2][4];
    #pragma unroll
    for (int mt = 0; mt < 2; mt++) {
        u32 ao = (u32)(arow + mt * 16) * 528 + (u32)(kg + akof) * 2;
        ldsm4(ah[mt][0], ah[mt][1], ah[mt][2], ah[mt][3], sb + XH_OFF + ao);
        ldsm4(al[mt][0], al[mt][1], al[mt][2], al[mt][3], sb + XL_OFF + ao);
    }
    #pragma unroll
    for (int nt = 0; nt < 8; nt++) {
        u32 b0, b1, b2, b3;
        ldsm4(b0, b1, b2, b3, bbase + (u32)(nbase + nt * 8 + bl8) * 144);
        #pragma unroll
        for (int mt = 0; mt < 2; mt++) {
            mma_bf16(acc[mt][nt], ah[mt][0], ah[mt][1], ah[mt][2], ah[mt][3], b0, b1);
            mma_bf16(acc[mt][nt], al[mt][0], al[mt][1], al[mt][2], al[mt][3], b0, b1);
            mma_bf16(acc[mt][nt], ah[mt][0], ah[mt][1], ah[mt][2], ah[mt][3], b2, b3);
        }
    }
}

// ---------------------------------------------------------------------------
// mmaA: g_A = anchor @ W1x^T + b1 (bf16 split MMA, 64 rows/CTA, 256 threads)
// ---------------------------------------------------------------------------
__global__ void __launch_bounds__(256, 1)
mmaA(const float* __restrict__ anchor, const float* __restrict__ b1) {
    extern __shared__ char smc[];
    const u32 sb = smem_u32(smc);
    const int tid = threadIdx.x, lane = tid & 31, wid = tid >> 5;
    const int r0 = blockIdx.x * 64;
    const int mbase = (wid >> 2) * 32;
    const int nbase = (wid & 3) * 64;

    for (int i = tid; i < 4096; i += 256) {
        int row = i >> 6, q = i & 63;
        float4 v = ((const float4*)(anchor + (size_t)(r0 + row) * 256))[q];
        split_store(smc, (u32)row * 528 + q * 8, v);
    }
    stage_w(smc, g_W1xh, g_W1xl, 36864, tid);
    __syncthreads();

    float acc[2][8][4];
    #pragma unroll
    for (int mt = 0; mt < 2; mt++)
        #pragma unroll
        for (int nt = 0; nt < 8; nt++)
            #pragma unroll
            for (int q = 0; q < 4; q++) acc[mt][nt][q] = 0.f;

    for (int c = 0; c < 4; c++) {
        #pragma unroll
        for (int ks = 0; ks < 4; ks++)
            l1_kstep(sb, c * 64 + ks * 16, ks * 16, mbase, nbase, lane, acc);
        __syncthreads();
        if (c < 3) {
            stage_w(smc, g_W1xh + (c + 1) * 36864, g_W1xl + (c + 1) * 36864, 36864, tid);
            __syncthreads();
        }
    }

    const int row0 = mbase + (lane >> 2);
    const int col0 = nbase + (lane & 3) * 2;
    #pragma unroll
    for (int mt = 0; mt < 2; mt++)
        #pragma unroll
        for (int nt = 0; nt < 8; nt++) {
            int col = col0 + nt * 8;
            float2 bb = *(const float2*)(b1 + col);
            #pragma unroll
            for (int h = 0; h < 2; h++) {
                int rr = row0 + mt * 16 + h * 8;
                float2 v = {acc[mt][nt][2 * h] + bb.x, acc[mt][nt][2 * h + 1] + bb.y};
                *(float2*)(g_A + (size_t)(r0 + rr) * 256 + col) = v;
            }
        }
}

// ---------------------------------------------------------------------------
// energyT: fused 4-layer MLP on tensor cores, 64 rows per CTA (R6 proven)
// ---------------------------------------------------------------------------
__global__ void __launch_bounds__(256, 1)
energyT(const float* __restrict__ positive, const float* __restrict__ negatives,
        const float* __restrict__ b2, const float* __restrict__ b3,
        const float* __restrict__ W4, const float* __restrict__ b4) {
    extern __shared__ char smc[];
    const u32 sb = smem_u32(smc);
    const int tid = threadIdx.x, lane = tid & 31, wid = tid >> 5;
    const int r0 = blockIdx.x * 64;
    const int mbase = (wid >> 2) * 32;
    const int row0 = mbase + (lane >> 2);
    const int col0 = (lane & 3) * 2;
    const int arow = mbase + (lane & 15);
    const int akof = (lane & 16) ? 8 : 0;
    const int bl8 = lane & 7;
    const int bk8 = lane & 8;
    const u32 bsel = (lane < 16) ? (sb + WH_OFF) : (sb + WL_OFF);

    // ---- stage Y tile (split) + W1y chunk 0
    for (int i = tid; i < 4096; i += 256) {
        int row = i >> 6, q = i & 63;
        int g = r0 + row, b = g / 17, j = g - b * 17;
        const float* src = j ? negatives + ((size_t)(b * 16 + j - 1)) * 256
                             : positive + (size_t)b * 256;
        split_store(smc, (u32)row * 528 + q * 8, ((const float4*)src)[q]);
    }
    stage_w(smc, g_W1yh, g_W1yl, 36864, tid);
    __syncthreads();

    // ================= Layer 1: 64x256, K=256 ===============================
    {
        const int nbase = (wid & 3) * 64;
        float acc[2][8][4];
        #pragma unroll
        for (int mt = 0; mt < 2; mt++)
            #pragma unroll
            for (int nt = 0; nt < 8; nt++)
                #pragma unroll
                for (int q = 0; q < 4; q++) acc[mt][nt][q] = 0.f;

        for (int c = 0; c < 4; c++) {
            #pragma unroll
            for (int ks = 0; ks < 4; ks++)
                l1_kstep(sb, c * 64 + ks * 16, ks * 16, mbase, nbase, lane, acc);
            __syncthreads();
            if (c < 3) {
                stage_w(smc, g_W1yh + (c + 1) * 36864, g_W1yl + (c + 1) * 36864, 36864, tid);
                __syncthreads();
            }
        }
        // epilogue: + g_A, GELU, split -> H1
        #pragma unroll
        for (int mt = 0; mt < 2; mt++)
            #pragma unroll
            for (int nt = 0; nt < 8; nt++) {
                int col = nbase + nt * 8 + col0;
                #pragma unroll
                for (int h = 0; h < 2; h++) {
                    int rr = row0 + mt * 16 + h * 8;
                    int gb = (r0 + rr) / 17;
                    float2 a = *(const float2*)(g_A + (size_t)gb * 256 + col);
                    float v0 = gelu_exact(acc[mt][nt][2 * h] + a.x);
                    float v1 = gelu_exact(acc[mt][nt][2 * h + 1] + a.y);
                    u32 off = (u32)rr * 528 + col * 2;
                    *(u32*)(smc + H1H_OFF + off) = bfpair(v0, v1);
                    *(u32*)(smc + H1L_OFF + off) = bfpair(v0 - bfhi(v0), v1 - bfhi(v1));
                }
            }
    }
    stage_w(smc, g_W2h, g_W2l, 18432, tid);
    __syncthreads();

    // ================= Layer 2: 64x128, K=256 ===============================
    {
        const int nbase = (wid & 3) * 32;
        float acc[2][4][4];
        #pragma unroll
        for (int mt = 0; mt < 2; mt++)
            #pragma unroll
            for (int nt = 0; nt < 4; nt++)
                #pragma unroll
                for (int q = 0; q < 4; q++) acc[mt][nt][q] = 0.f;

        for (int c = 0; c < 4; c++) {
            #pragma unroll
            for (int ks = 0; ks < 4; ks++) {
                int kg = c * 64 + ks * 16, kl = ks * 16;
                u32 ah[2][4], al[2][4];
                #pragma unroll
                for (int mt = 0; mt < 2; mt++) {
                    u32 ao = (u32)(arow + mt * 16) * 528 + (u32)(kg + akof) * 2;
                    ldsm4(ah[mt][0], ah[mt][1], ah[mt][2], ah[mt][3], sb + H1H_OFF + ao);
                    ldsm4(al[mt][0], al[mt][1], al[mt][2], al[mt][3], sb + H1L_OFF + ao);
                }
                u32 bb = bsel + (u32)(kl + bk8) * 2;
                #pragma unroll
                for (int nt = 0; nt < 4; nt++) {
                    u32 b0, b1, b2, b3;
                    ldsm4(b0, b1, b2, b3, bb + (u32)(nbase + nt * 8 + bl8) * 144);
                    #pragma unroll
                    for (int mt = 0; mt < 2; mt++) {
                        mma_bf16(acc[mt][nt], ah[mt][0], ah[mt][1], ah[mt][2], ah[mt][3], b0, b1);
                        mma_bf16(acc[mt][nt], al[mt][0], al[mt][1], al[mt][2], al[mt][3], b0, b1);
                        mma_bf16(acc[mt][nt], ah[mt][0], ah[mt][1], ah[mt][2], ah[mt][3], b2, b3);
                    }
                }
            }
            __syncthreads();
            if (c < 3) {
                stage_w(smc, g_W2h + (c + 1) * 18432, g_W2l + (c + 1) * 18432, 18432, tid);
                __syncthreads();
            }
        }
        // epilogue -> H2 (into old X region; X no longer read)
        #pragma unroll
        for (int mt = 0; mt < 2; mt++)
            #pragma unroll
            for (int nt = 0; nt < 4; nt++) {
                int col = nbase + nt * 8 + col0;
                float2 bb = *(const float2*)(b2 + col);
                #pragma unroll
                for (int h = 0; h < 2; h++) {
                    int rr = row0 + mt * 16 + h * 8;
                    float v0 = gelu_exact(acc[mt][nt][2 * h] + bb.x);
                    float v1 = gelu_exact(acc[mt][nt][2 * h + 1] + bb.y);
                    u32 off = (u32)rr * 272 + col * 2;
                    *(u32*)(smc + H2H_OFF + off) = bfpair(v0, v1);
                    *(u32*)(smc + H2L_OFF + off) = bfpair(v0 - bfhi(v0), v1 - bfhi(v1));
                }
            }
    }
    stage_w(smc, g_W3h, g_W3l, 17408, tid);
    if (tid < 64) ((float*)(smc + W4_OFF))[tid] = W4[tid];
    __syncthreads();

    // ================= Layer 3: 64x64, K=128 ================================
    {
        const int nbase = (wid & 3) * 16;
        float acc[2][2][4];
        #pragma unroll
        for (int mt = 0; mt < 2; mt++)
            #pragma unroll
            for (int nt = 0; nt < 2; nt++)
                #pragma unroll
                for (int q = 0; q < 4; q++) acc[mt][nt][q] = 0.f;

        #pragma unroll
        for (int ks = 0; ks < 8; ks++) {
            int k0 = ks * 16;
            u32 ah[2][4], al[2][4];
            #pragma unroll
            for (int mt = 0; mt < 2; mt++) {
                u32 ao = (u32)(arow + mt * 16) * 272 + (u32)(k0 + akof) * 2;
                ldsm4(ah[mt][0], ah[mt][1], ah[mt][2], ah[mt][3], sb + H2H_OFF + ao);
                ldsm4(al[mt][0], al[mt][1], al[mt][2], al[mt][3], sb + H2L_OFF + ao);
            }
            u32 bb = bsel + (u32)(k0 + bk8) * 2;
            #pragma unroll
            for (int nt = 0; nt < 2; nt++) {
                u32 b0, b1, b2, b3;
                ldsm4(b0, b1, b2, b3, bb + (u32)(nbase + nt * 8 + bl8) * 272);
                #pragma unroll
                for (int mt = 0; mt < 2; mt++) {
                    mma_bf16(acc[mt][nt], ah[mt][0], ah[mt][1], ah[mt][2], ah[mt][3], b0, b1);
                    mma_bf16(acc[mt][nt], al[mt][0], al[mt][1], al[mt][2], al[mt][3], b0, b1);
                    mma_bf16(acc[mt][nt], ah[mt][0], ah[mt][1], ah[mt][2], ah[mt][3], b2, b3);
                }
            }
        }
        // epilogue -> H3 fp32 (disjoint from H2)
        float* H3 = (float*)(smc + H3_OFF);
        #pragma unroll
        for (int mt = 0; mt < 2; mt++)
            #pragma unroll
            for (int nt = 0; nt < 2; nt++) {
                int col = nbase + nt * 8 + col0;
                float2 bb = *(const float2*)(b3 + col);
                #pragma unroll
                for (int h = 0; h < 2; h++) {
                    int rr = row0 + mt * 16 + h * 8;
                    float2 v = {gelu_exact(acc[mt][nt][2 * h] + bb.x),
                                gelu_exact(acc[mt][nt][2 * h + 1] + bb.y)};
                    *(float2*)(H3 + rr * 68 + col) = v;
                }
            }
    }
    __syncthreads();

    // ================= Layer 4: dot(64) =====================================
    if (tid < 64) {
        const float* H3 = (const float*)(smc + H3_OFF);
        const float* w4 = (const float*)(smc + W4_OFF);
        float e = b4[0];
        #pragma unroll
        for (int k = 0; k < 64; k++) e += H3[tid * 68 + k] * w4[k];
        g_energy[r0 + tid] = e;
    }
}

// ---------------------------------------------------------------------------
// flagK: compact list of near-tie batches (set is deterministic; order not
// needed — fixup2 overwrites all 17 energies of each flagged batch)
// ---------------------------------------------------------------------------
__global__ void flagK() {
    int b = blockIdx.x * 256 + threadIdx.x;
    const float* e = &g_energy[(size_t)b * 17];
    float mn = e[1];
    #pragma unroll
    for (int j = 2; j < 17; j++) mn = fminf(mn, e[j]);
    if (fabsf(e[0] - mn) < FIX_THRESH) {
        int p = atomicAdd(&g_cnt, 1);
        g_list[p] = b;
    }
}

// ---------------------------------------------------------------------------
// fixup2: persistent; one (batch, candidate) energy per work item, exact fp32.
// Warp-per-output coalesced dots.
// ---------------------------------------------------------------------------
__global__ void __launch_bounds__(128)
fixup2(const float* __restrict__ anchor, const float* __restrict__ positive,
       const float* __restrict__ negatives,
       const float* __restrict__ W1, const float* __restrict__ b1,
       const float* __restrict__ W2, const float* __restrict__ b2,
       const float* __restrict__ W3, const float* __restrict__ b3,
       const float* __restrict__ W4, const float* __restrict__ b4) {
    __shared__ float xy[512], h1[256], h2[128], h3[64];
    const int tid = threadIdx.x, lane = tid & 31, wid = tid >> 5;
    const int nwork = g_cnt * 17;

    for (int idx = blockIdx.x; idx < nwork; idx += FIXGRID) {
        int q = idx / 17;
        int j = idx - q * 17;
        int b = g_list[q];
        const float* ysrc = j ? negatives + ((size_t)(b * 16 + j - 1)) * 256
                              : positive + (size_t)b * 256;
        for (int i = tid; i < 256; i += 128) {
            xy[i]       = anchor[(size_t)b * 256 + i];
            xy[256 + i] = ysrc[i];
        }
        __syncthreads();

        // L1: 256 outs over 4 warps, lanes parallel over K=512
        for (int o = wid; o < 256; o += 4) {
            const float* w = W1 + (size_t)o * 512;
            float acc = 0.f;
            #pragma unroll
            for (int i = 0; i < 16; i++) acc += w[lane + 32 * i] * xy[lane + 32 * i];
            #pragma unroll
            for (int s = 16; s; s >>= 1) acc += __shfl_xor_sync(0xFFFFFFFFu, acc, s);
            if (lane == 0) h1[o] = gelu_exact(acc + b1[o]);
        }
        __syncthreads();

        // L2: 128 outs, K=256
        for (int o = wid; o < 128; o += 4) {
            const float* w = W2 + (size_t)o * 256;
            float acc = 0.f;
            #pragma unroll
            for (int i = 0; i < 8; i++) acc += w[lane + 32 * i] * h1[lane + 32 * i];
            #pragma unroll
            for (int s = 16; s; s >>= 1) acc += __shfl_xor_sync(0xFFFFFFFFu, acc, s);
            if (lane == 0) h2[o] = gelu_exact(acc + b2[o]);
        }
        __syncthreads();

        // L3: 64 outs, K=128; fold in W4
        for (int o = wid; o < 64; o += 4) {
            const float* w = W3 + (size_t)o * 128;
            float acc = 0.f;
            #pragma unroll
            for (int i = 0; i < 4; i++) acc += w[lane + 32 * i] * h2[lane + 32 * i];
            #pragma unroll
            for (int s = 16; s; s >>= 1) acc += __shfl_xor_sync(0xFFFFFFFFu, acc, s);
            if (lane == 0) h3[o] = gelu_exact(acc + b3[o]) * W4[o];
        }
        __syncthreads();

        if (wid == 0) {
            float acc = h3[lane] + h3[lane + 32];
            #pragma unroll
            for (int s = 16; s; s >>= 1) acc += __shfl_xor_sync(0xFFFFFFFFu, acc, s);
            if (lane == 0) g_energy[(size_t)b * 17 + j] = acc + b4[0];
        }
        __syncthreads();
    }
}

// ---------------------------------------------------------------------------
// reductions (deterministic, unchanged)
// ---------------------------------------------------------------------------
__global__ void reduce1() {
    __shared__ float sl[256], sp[256], sn[256], sa[256];
    const int t = threadIdx.x;
    const int b = blockIdx.x * 256 + t;
    const float* e = &g_energy[(size_t)b * 17];

    float v[17];
    #pragma unroll
    for (int j = 0; j < 17; j++) v[j] = e[j];

    float l0 = -v[0] * TEMP_INV;
    float mx = l0;
    #pragma unroll
    for (int j = 1; j < 17; j++) mx = fmaxf(mx, -v[j] * TEMP_INV);
    float s = 0.f;
    #pragma unroll
    for (int j = 0; j < 17; j++) s += expf(-v[j] * TEMP_INV - mx);
    float loss = mx + logf(s) - l0;

    float pos = v[0], neg = 0.f, ok = 1.f;
    #pragma unroll
    for (int j = 1; j < 17; j++) {
        neg += v[j];
        if (v[j] < v[0]) ok = 0.f;
    }

    sl[t] = loss; sp[t] = pos; sn[t] = neg; sa[t] = ok;
    __syncthreads();
    for (int st = 128; st > 0; st >>= 1) {
        if (t < st) {
            sl[t] += sl[t + st]; sp[t] += sp[t + st];
            sn[t] += sn[t + st]; sa[t] += sa[t + st];
        }
        __syncthreads();
    }
    if (t == 0) {
        g_part[blockIdx.x][0] = sl[0];
        g_part[blockIdx.x][1] = sp[0];
        g_part[blockIdx.x][2] = sn[0];
        g_part[blockIdx.x][3] = sa[0];
    }
}

__global__ void reduce2(float* __restrict__ out) {
    __shared__ float s[128][4];
    const int t = threadIdx.x;
    #pragma unroll
    for (int c = 0; c < 4; c++) s[t][c] = g_part[t][c];
    __syncthreads();
    for (int st = 64; st > 0; st >>= 1) {
        if (t < st) {
            #pragma unroll
            for (int c = 0; c < 4; c++) s[t][c] += s[t + st][c];
        }
        __syncthreads();
    }
    if (t == 0) {
        out[0] = s[0][0] / 32768.0f;
        out[1] = s[0][1] / 32768.0f;
        out[2] = s[0][2] / (32768.0f * 16.0f);
        out[3] = s[0][3] / 32768.0f;
    }
}

// ---------------------------------------------------------------------------
extern "C" void kernel_launch(void* const* d_in, const int* in_sizes, int n_in,
                              void* d_out, int out_size) {
    const float* anchor    = (const float*)d_in[0];
    const float* positive  = (const float*)d_in[1];
    const float* negatives = (const float*)d_in[2];
    const float* W1 = (const float*)d_in[3];
    const float* b1 = (const float*)d_in[4];
    const float* W2 = (const float*)d_in[5];
    const float* b2 = (const float*)d_in[6];
    const float* W3 = (const float*)d_in[7];
    const float* b3 = (const float*)d_in[8];
    const float* W4 = (const float*)d_in[9];
    const float* b4 = (const float*)d_in[10];
    float* out = (float*)d_out;

    cudaFuncSetAttribute(mmaA,    cudaFuncAttributeMaxDynamicSharedMemorySize, SMEM_A);
    cudaFuncSetAttribute(energyT, cudaFuncAttributeMaxDynamicSharedMemorySize, SMEM_EN);

    prepW_a<<<512, 256>>>(W1);                                      // 1 (zeros g_cnt)
    prepW_b<<<160, 256>>>(W2, W3);                                  // 2
    mmaA<<<NB / 64, 256, SMEM_A>>>(anchor, b1);                     // 3
    energyT<<<NBLK, 256, SMEM_EN>>>(positive, negatives, b2, b3, W4, b4); // 4 (profiled)
    flagK<<<NB / 256, 256>>>();                                     // 5
    fixup2<<<FIXGRID, 128>>>(anchor, positive, negatives,
                             W1, b1, W2, b2, W3, b3, W4, b4);       // 6
    reduce1<<<128, 256>>>();                                        // 7
    reduce2<<<1, 128>>>(out);                                       // 8
}

// round 9
// speedup vs baseline: 44.3267x; 1.4851x over previous
#include <cuda_runtime.h>
#include <cuda_bf16.h>
#include <math.h>

// ---------------------------------------------------------------------------
// ContrastiveEnergyLearning — Round 9: 128-row CTAs (256 thr) + cp.async
// double-buffered weight streaming (32-K chunks, 80B pitch). 3-term bf16
// split MMA + exact-fp32 parallel fixup (unchanged numerics from R8).
// ---------------------------------------------------------------------------

#define NB 32768
#define RTOT (NB * 17)            // 557056
#define NBLK (RTOT / 128)         // 4352
#define TEMP_INV (1.0f / 0.07f)
#define FIX_THRESH 5e-4f
#define FIXGRID 2048

__device__ float g_A[NB * 256];
__device__ float g_energy[RTOT];
__device__ float g_part[128][4];
__device__ int   g_cnt;
__device__ int   g_list[NB];

// prepped bf16 hi/lo weights: [chunk32][out][40 bf16] (pitch 80B)
__device__ unsigned char g_W1xh[163840], g_W1xl[163840];  // 8 x 256 x 80
__device__ unsigned char g_W1yh[163840], g_W1yl[163840];
__device__ unsigned char g_W2h[81920],   g_W2l[81920];    // 8 x 128 x 80
__device__ unsigned char g_W3h[20480],   g_W3l[20480];    // 4 x 64 x 80

typedef unsigned int u32;

// ---------------- helpers ---------------------------------------------------
__device__ __forceinline__ float gelu_exact(float x) {
    return 0.5f * x * (1.0f + erff(x * 0.7071067811865476f));
}
__device__ __forceinline__ u32 bfpair(float a, float b) {
    __nv_bfloat162 t = __floats2bfloat162_rn(a, b);
    return *(u32*)&t;
}
__device__ __forceinline__ float bfhi(float a) {
    return __bfloat162float(__float2bfloat16_rn(a));
}
__device__ __forceinline__ u32 smem_u32(const void* p) {
    u32 a;
    asm("{ .reg .u64 t; cvta.to.shared.u64 t, %1; cvt.u32.u64 %0, t; }"
        : "=r"(a) : "l"(p));
    return a;
}
__device__ __forceinline__ void ldsm4(u32& r0, u32& r1, u32& r2, u32& r3, u32 a) {
    asm volatile("ldmatrix.sync.aligned.m8n8.x4.shared.b16 {%0,%1,%2,%3},[%4];"
                 : "=r"(r0), "=r"(r1), "=r"(r2), "=r"(r3) : "r"(a));
}
__device__ __forceinline__ void mma_bf16(float d[4], const u32 a[4], u32 b0, u32 b1) {
    asm volatile("mma.sync.aligned.m16n8k16.row.col.f32.bf16.bf16.f32 "
                 "{%0,%1,%2,%3},{%4,%5,%6,%7},{%8,%9},{%0,%1,%2,%3};"
                 : "+f"(d[0]), "+f"(d[1]), "+f"(d[2]), "+f"(d[3])
                 : "r"(a[0]), "r"(a[1]), "r"(a[2]), "r"(a[3]), "r"(b0), "r"(b1));
}
__device__ __forceinline__ void cpa16(u32 dst, const void* src) {
    asm volatile("cp.async.cg.shared.global [%0],[%1],16;" :: "r"(dst), "l"(src));
}
#define CP_COMMIT() asm volatile("cp.async.commit_group;" ::: "memory")
#define CP_WAIT0()  asm volatile("cp.async.wait_group 0;" ::: "memory")

// ---------------- SMEM layout (bytes) ---------------------------------------
// [0,135168): XH/H1H (128x528) @0 ; XL/H1L @67584
//   after L2: H2H @0, H2L @34816 (128x272 each); H3 @69632 (128x68 f32); W4 @104448
// [135168,217088): weight double buffer (2 x 40960)
#define REG_X   0u
#define REG_XL  67584u
#define H2H_OFF 0u
#define H2L_OFF 34816u
#define H3_OFF  69632u
#define W4_OFF  104448u
#define WBUF0   135168u
#define WBUF1   176128u
#define SMEM_EN 217088

// ---------------------------------------------------------------------------
// prep kernels: split fp32 -> bf16 hi/lo into [chunk32][out][40] pitch-80 tiles
// ---------------------------------------------------------------------------
__global__ void prepW_a(const float* __restrict__ W1) {
    int i = blockIdx.x * 256 + threadIdx.x;          // 131072 items
    if (i == 0) g_cnt = 0;
    if (i >= 131072) return;
    int half = i >> 16;
    int j = i & 65535;
    int o = j >> 8, k = j & 255;
    float w = W1[o * 512 + half * 256 + k];
    u32 off = ((u32)(k >> 5) * 256 + o) * 80 + (k & 31) * 2;
    __nv_bfloat16 h = __float2bfloat16_rn(w);
    __nv_bfloat16 l = __float2bfloat16_rn(w - __bfloat162float(h));
    unsigned char* dh = half ? g_W1yh : g_W1xh;
    unsigned char* dl = half ? g_W1yl : g_W1xl;
    *(__nv_bfloat16*)(dh + off) = h;
    *(__nv_bfloat16*)(dl + off) = l;
}

__global__ void prepW_b(const float* __restrict__ W2, const float* __restrict__ W3) {
    int i = blockIdx.x * 256 + threadIdx.x;          // 40960 items
    float w; unsigned char *dh, *dl; u32 off;
    if (i < 32768) {
        int o = i >> 8, k = i & 255;
        w = W2[o * 256 + k];
        off = ((u32)(k >> 5) * 128 + o) * 80 + (k & 31) * 2;
        dh = g_W2h; dl = g_W2l;
    } else if (i < 40960) {
        int j = i - 32768;
        int o = j >> 7, k = j & 127;
        w = W3[o * 128 + k];
        off = ((u32)(k >> 5) * 64 + o) * 80 + (k & 31) * 2;
        dh = g_W3h; dl = g_W3l;
    } else return;
    __nv_bfloat16 h = __float2bfloat16_rn(w);
    __nv_bfloat16 l = __float2bfloat16_rn(w - __bfloat162float(h));
    *(__nv_bfloat16*)(dh + off) = h;
    *(__nv_bfloat16*)(dl + off) = l;
}

// ---------------- cp.async chunk issue ---------------------------------------
__device__ __forceinline__ void issue_chunk(u32 sb, u32 buf, const unsigned char* gh,
                                            const unsigned char* gl, int hb, int tid) {
    for (int i = tid * 16; i < hb; i += 4096) {
        cpa16(sb + buf + i, gh + i);
        cpa16(sb + buf + hb + i, gl + i);
    }
    CP_COMMIT();
}

// ---------------------------------------------------------------------------
// generic 3-term kstep: MT m-tiles, NT n-tiles
//   A: smem K-major pitch AP, hi at aoffH, lo at aoffL, k base kg
//   B: weight buffer at wb, h-bytes HB, local k base kk
// ---------------------------------------------------------------------------
template <int MT, int NT>
__device__ __forceinline__ void kstepG(u32 sb, u32 aoffH, u32 aoffL, u32 AP, int kg,
                                       u32 wb, int HB, int kk, int nbase,
                                       int arow, int akof, int bl8, int bk8, int lane,
                                       float acc[MT][NT][4]) {
    u32 ah[MT][4], al[MT][4];
    #pragma unroll
    for (int mt = 0; mt < MT; mt++) {
        u32 ao = (u32)(arow + mt * 16) * AP + (u32)(kg + akof) * 2;
        ldsm4(ah[mt][0], ah[mt][1], ah[mt][2], ah[mt][3], sb + aoffH + ao);
        ldsm4(al[mt][0], al[mt][1], al[mt][2], al[mt][3], sb + aoffL + ao);
    }
    const u32 bb = sb + wb + (u32)((lane < 16) ? 0 : HB) + (u32)(kk + bk8) * 2;
    #pragma unroll
    for (int nt = 0; nt < NT; nt++) {
        u32 b0, b1, b2, b3;
        ldsm4(b0, b1, b2, b3, bb + (u32)(nbase + nt * 8 + bl8) * 80);
        #pragma unroll
        for (int mt = 0; mt < MT; mt++) {
            mma_bf16(acc[mt][nt], ah[mt], b0, b1);
            mma_bf16(acc[mt][nt], al[mt], b0, b1);
            mma_bf16(acc[mt][nt], ah[mt], b2, b3);
        }
    }
}

__device__ __forceinline__ void split_storeX(char* smc, u32 off, float4 v) {
    uint2 hh, ll;
    hh.x = bfpair(v.x, v.y); hh.y = bfpair(v.z, v.w);
    ll.x = bfpair(v.x - bfhi(v.x), v.y - bfhi(v.y));
    ll.y = bfpair(v.z - bfhi(v.z), v.w - bfhi(v.w));
    *(uint2*)(smc + REG_X + off) = hh;
    *(uint2*)(smc + REG_XL + off) = ll;
}

// ---------------------------------------------------------------------------
// mmaA: g_A = anchor @ W1x^T + b1 (128 rows/CTA, streamed weights)
// ---------------------------------------------------------------------------
__global__ void __launch_bounds__(256, 1)
mmaA(const float* __restrict__ anchor, const float* __restrict__ b1) {
    extern __shared__ char smc[];
    const u32 sb = smem_u32(smc);
    const int tid = threadIdx.x, lane = tid & 31, wid = tid >> 5;
    const int r0 = blockIdx.x * 128;
    const int mbase = (wid >> 2) * 64;
    const int nbase = (wid & 3) * 64;
    const int arow = mbase + (lane & 15);
    const int akof = (lane & 16) ? 8 : 0;
    const int bl8 = lane & 7, bk8 = lane & 8;

    issue_chunk(sb, WBUF0, g_W1xh, g_W1xl, 20480, tid);

    for (int i = tid; i < 128 * 64; i += 256) {
        int row = i >> 6, q = i & 63;
        float4 v = ((const float4*)(anchor + (size_t)(r0 + row) * 256))[q];
        split_storeX(smc, (u32)row * 528 + q * 8, v);
    }

    float acc[4][8][4];
    #pragma unroll
    for (int mt = 0; mt < 4; mt++)
        #pragma unroll
        for (int nt = 0; nt < 8; nt++)
            #pragma unroll
            for (int q = 0; q < 4; q++) acc[mt][nt][q] = 0.f;

    for (int c = 0; c < 8; c++) {
        const u32 wb = (c & 1) ? WBUF1 : WBUF0;
        CP_WAIT0();
        __syncthreads();
        if (c < 7)
            issue_chunk(sb, (c & 1) ? WBUF0 : WBUF1,
                        g_W1xh + (c + 1) * 20480, g_W1xl + (c + 1) * 20480, 20480, tid);
        #pragma unroll
        for (int ks = 0; ks < 2; ks++)
            kstepG<4, 8>(sb, REG_X, REG_XL, 528, c * 32 + ks * 16,
                         wb, 20480, ks * 16, nbase, arow, akof, bl8, bk8, lane, acc);
    }

    const int row0 = mbase + (lane >> 2);
    const int col0 = nbase + (lane & 3) * 2;
    #pragma unroll
    for (int mt = 0; mt < 4; mt++)
        #pragma unroll
        for (int nt = 0; nt < 8; nt++) {
            int col = col0 + nt * 8;
            float2 bb = *(const float2*)(b1 + col);
            #pragma unroll
            for (int h = 0; h < 2; h++) {
                int rr = row0 + mt * 16 + h * 8;
                float2 v = {acc[mt][nt][2 * h] + bb.x, acc[mt][nt][2 * h + 1] + bb.y};
                *(float2*)(g_A + (size_t)(r0 + rr) * 256 + col) = v;
            }
        }
}

// ---------------------------------------------------------------------------
// energyT: fused 4-layer MLP, 128 rows/CTA, streamed weights
// ---------------------------------------------------------------------------
__global__ void __launch_bounds__(256, 1)
energyT(const float* __restrict__ positive, const float* __restrict__ negatives,
        const float* __restrict__ b2, const float* __restrict__ b3,
        const float* __restrict__ W4, const float* __restrict__ b4) {
    extern __shared__ char smc[];
    const u32 sb = smem_u32(smc);
    const int tid = threadIdx.x, lane = tid & 31, wid = tid >> 5;
    const int r0 = blockIdx.x * 128;
    const int mbase = (wid >> 2) * 64;
    const int row0 = mbase + (lane >> 2);
    const int col0 = (lane & 3) * 2;
    const int arow = mbase + (lane & 15);
    const int akof = (lane & 16) ? 8 : 0;
    const int bl8 = lane & 7, bk8 = lane & 8;

    issue_chunk(sb, WBUF0, g_W1yh, g_W1yl, 20480, tid);

    // stage Y tile (split hi/lo)
    for (int i = tid; i < 128 * 64; i += 256) {
        int row = i >> 6, q = i & 63;
        int g = r0 + row, b = g / 17, j = g - b * 17;
        const float* src = j ? negatives + ((size_t)(b * 16 + j - 1)) * 256
                             : positive + (size_t)b * 256;
        split_storeX(smc, (u32)row * 528 + q * 8, ((const float4*)src)[q]);
    }

    // ================= Layer 1: 128x256, K=256, 8 chunks ====================
    {
        const int nbase = (wid & 3) * 64;
        float acc[4][8][4];
        #pragma unroll
        for (int mt = 0; mt < 4; mt++)
            #pragma unroll
            for (int nt = 0; nt < 8; nt++)
                #pragma unroll
                for (int q = 0; q < 4; q++) acc[mt][nt][q] = 0.f;

        for (int c = 0; c < 8; c++) {
            const u32 wb = (c & 1) ? WBUF1 : WBUF0;
            CP_WAIT0();
            __syncthreads();
            if (c < 7)
                issue_chunk(sb, (c & 1) ? WBUF0 : WBUF1,
                            g_W1yh + (c + 1) * 20480, g_W1yl + (c + 1) * 20480, 20480, tid);
            else
                issue_chunk(sb, WBUF0, g_W2h, g_W2l, 10240, tid);  // L2 chunk 0 (buf parity even)
            #pragma unroll
            for (int ks = 0; ks < 2; ks++)
                kstepG<4, 8>(sb, REG_X, REG_XL, 528, c * 32 + ks * 16,
                             wb, 20480, ks * 16, nbase, arow, akof, bl8, bk8, lane, acc);
        }
        __syncthreads();   // all X reads done; X region becomes H1
        #pragma unroll
        for (int mt = 0; mt < 4; mt++)
            #pragma unroll
            for (int nt = 0; nt < 8; nt++) {
                int col = nbase + nt * 8 + col0;
                #pragma unroll
                for (int h = 0; h < 2; h++) {
                    int rr = row0 + mt * 16 + h * 8;
                    int gb = (r0 + rr) / 17;
                    float2 a = *(const float2*)(g_A + (size_t)gb * 256 + col);
                    float v0 = gelu_exact(acc[mt][nt][2 * h] + a.x);
                    float v1 = gelu_exact(acc[mt][nt][2 * h + 1] + a.y);
                    u32 off = (u32)rr * 528 + col * 2;
                    *(u32*)(smc + REG_X + off)  = bfpair(v0, v1);
                    *(u32*)(smc + REG_XL + off) = bfpair(v0 - bfhi(v0), v1 - bfhi(v1));
                }
            }
    }

    // ================= Layer 2: 128x128, K=256, 8 chunks ====================
    {
        const int nbase = (wid & 3) * 32;
        float acc[4][4][4];
        #pragma unroll
        for (int mt = 0; mt < 4; mt++)
            #pragma unroll
            for (int nt = 0; nt < 4; nt++)
                #pragma unroll
                for (int q = 0; q < 4; q++) acc[mt][nt][q] = 0.f;

        for (int c = 0; c < 8; c++) {
            const u32 wb = (c & 1) ? WBUF1 : WBUF0;
            CP_WAIT0();
            __syncthreads();   // first iter also publishes H1 stores
            if (c < 7)
                issue_chunk(sb, (c & 1) ? WBUF0 : WBUF1,
                            g_W2h + (c + 1) * 10240, g_W2l + (c + 1) * 10240, 10240, tid);
            else
                issue_chunk(sb, WBUF0, g_W3h, g_W3l, 5120, tid);   // L3 chunk 0
            #pragma unroll
            for (int ks = 0; ks < 2; ks++)
                kstepG<4, 4>(sb, REG_X, REG_XL, 528, c * 32 + ks * 16,
                             wb, 10240, ks * 16, nbase, arow, akof, bl8, bk8, lane, acc);
        }
        __syncthreads();   // H1 reads done; regions become H2/H3
        #pragma unroll
        for (int mt = 0; mt < 4; mt++)
            #pragma unroll
            for (int nt = 0; nt < 4; nt++) {
                int col = nbase + nt * 8 + col0;
                float2 bb = *(const float2*)(b2 + col);
                #pragma unroll
                for (int h = 0; h < 2; h++) {
                    int rr = row0 + mt * 16 + h * 8;
                    float v0 = gelu_exact(acc[mt][nt][2 * h] + bb.x);
                    float v1 = gelu_exact(acc[mt][nt][2 * h + 1] + bb.y);
                    u32 off = (u32)rr * 272 + col * 2;
                    *(u32*)(smc + H2H_OFF + off) = bfpair(v0, v1);
                    *(u32*)(smc + H2L_OFF + off) = bfpair(v0 - bfhi(v0), v1 - bfhi(v1));
                }
            }
        if (tid < 64) ((float*)(smc + W4_OFF))[tid] = W4[tid];
    }

    // ================= Layer 3: 128x64, K=128, 4 chunks =====================
    {
        const int nbase = (wid & 3) * 16;
        float acc[4][2][4];
        #pragma unroll
        for (int mt = 0; mt < 4; mt++)
            #pragma unroll
            for (int nt = 0; nt < 2; nt++)
                #pragma unroll
                for (int q = 0; q < 4; q++) acc[mt][nt][q] = 0.f;

        for (int c = 0; c < 4; c++) {
            const u32 wb = (c & 1) ? WBUF1 : WBUF0;
            CP_WAIT0();
            __syncthreads();   // first iter publishes H2 stores
            if (c < 3)
                issue_chunk(sb, (c & 1) ? WBUF0 : WBUF1,
                            g_W3h + (c + 1) * 5120, g_W3l + (c + 1) * 5120, 5120, tid);
            #pragma unroll
            for (int ks = 0; ks < 2; ks++)
                kstepG<4, 2>(sb, H2H_OFF, H2L_OFF, 272, c * 32 + ks * 16,
                             wb, 5120, ks * 16, nbase, arow, akof, bl8, bk8, lane, acc);
        }
        // epilogue -> H3 fp32 (region disjoint from H2)
        float* H3 = (float*)(smc + H3_OFF);
        #pragma unroll
        for (int mt = 0; mt < 4; mt++)
            #pragma unroll
            for (int nt = 0; nt < 2; nt++) {
                int col = nbase + nt * 8 + col0;
                float2 bb = *(const float2*)(b3 + col);
                #pragma unroll
                for (int h = 0; h < 2; h++) {
                    int rr = row0 + mt * 16 + h * 8;
                    float2 v = {gelu_exact(acc[mt][nt][2 * h] + bb.x),
                                gelu_exact(acc[mt][nt][2 * h + 1] + bb.y)};
                    *(float2*)(H3 + rr * 68 + col) = v;
                }
            }
    }
    __syncthreads();

    // ================= Layer 4: dot(64) =====================================
    if (tid < 128) {
        const float* H3 = (const float*)(smc + H3_OFF);
        const float* w4 = (const float*)(smc + W4_OFF);
        float e = b4[0];
        #pragma unroll
        for (int k = 0; k < 64; k++) e += H3[tid * 68 + k] * w4[k];
        g_energy[r0 + tid] = e;
    }
}

// ---------------------------------------------------------------------------
// flagK + fixup2 (unchanged from R8)
// ---------------------------------------------------------------------------
__global__ void flagK() {
    int b = blockIdx.x * 256 + threadIdx.x;
    const float* e = &g_energy[(size_t)b * 17];
    float mn = e[1];
    #pragma unroll
    for (int j = 2; j < 17; j++) mn = fminf(mn, e[j]);
    if (fabsf(e[0] - mn) < FIX_THRESH) {
        int p = atomicAdd(&g_cnt, 1);
        g_list[p] = b;
    }
}

__global__ void __launch_bounds__(128)
fixup2(const float* __restrict__ anchor, const float* __restrict__ positive,
       const float* __restrict__ negatives,
       const float* __restrict__ W1, const float* __restrict__ b1,
       const float* __restrict__ W2, const float* __restrict__ b2,
       const float* __restrict__ W3, const float* __restrict__ b3,
       const float* __restrict__ W4, const float* __restrict__ b4) {
    __shared__ float xy[512], h1[256], h2[128], h3[64];
    const int tid = threadIdx.x, lane = tid & 31, wid = tid >> 5;
    const int nwork = g_cnt * 17;

    for (int idx = blockIdx.x; idx < nwork; idx += FIXGRID) {
        int q = idx / 17;
        int j = idx - q * 17;
        int b = g_list[q];
        const float* ysrc = j ? negatives + ((size_t)(b * 16 + j - 1)) * 256
                              : positive + (size_t)b * 256;
        for (int i = tid; i < 256; i += 128) {
            xy[i]       = anchor[(size_t)b * 256 + i];
            xy[256 + i] = ysrc[i];
        }
        __syncthreads();

        for (int o = wid; o < 256; o += 4) {
            const float* w = W1 + (size_t)o * 512;
            float acc = 0.f;
            #pragma unroll
            for (int i = 0; i < 16; i++) acc += w[lane + 32 * i] * xy[lane + 32 * i];
            #pragma unroll
            for (int s = 16; s; s >>= 1) acc += __shfl_xor_sync(0xFFFFFFFFu, acc, s);
            if (lane == 0) h1[o] = gelu_exact(acc + b1[o]);
        }
        __syncthreads();

        for (int o = wid; o < 128; o += 4) {
            const float* w = W2 + (size_t)o * 256;
            float acc = 0.f;
            #pragma unroll
            for (int i = 0; i < 8; i++) acc += w[lane + 32 * i] * h1[lane + 32 * i];
            #pragma unroll
            for (int s = 16; s; s >>= 1) acc += __shfl_xor_sync(0xFFFFFFFFu, acc, s);
            if (lane == 0) h2[o] = gelu_exact(acc + b2[o]);
        }
        __syncthreads();

        for (int o = wid; o < 64; o += 4) {
            const float* w = W3 + (size_t)o * 128;
            float acc = 0.f;
            #pragma unroll
            for (int i = 0; i < 4; i++) acc += w[lane + 32 * i] * h2[lane + 32 * i];
            #pragma unroll
            for (int s = 16; s; s >>= 1) acc += __shfl_xor_sync(0xFFFFFFFFu, acc, s);
            if (lane == 0) h3[o] = gelu_exact(acc + b3[o]) * W4[o];
        }
        __syncthreads();

        if (wid == 0) {
            float acc = h3[lane] + h3[lane + 32];
            #pragma unroll
            for (int s = 16; s; s >>= 1) acc += __shfl_xor_sync(0xFFFFFFFFu, acc, s);
            if (lane == 0) g_energy[(size_t)b * 17 + j] = acc + b4[0];
        }
        __syncthreads();
    }
}

// ---------------------------------------------------------------------------
// reductions (unchanged)
// ---------------------------------------------------------------------------
__global__ void reduce1() {
    __shared__ float sl[256], sp[256], sn[256], sa[256];
    const int t = threadIdx.x;
    const int b = blockIdx.x * 256 + t;
    const float* e = &g_energy[(size_t)b * 17];

    float v[17];
    #pragma unroll
    for (int j = 0; j < 17; j++) v[j] = e[j];

    float l0 = -v[0] * TEMP_INV;
    float mx = l0;
    #pragma unroll
    for (int j = 1; j < 17; j++) mx = fmaxf(mx, -v[j] * TEMP_INV);
    float s = 0.f;
    #pragma unroll
    for (int j = 0; j < 17; j++) s += expf(-v[j] * TEMP_INV - mx);
    float loss = mx + logf(s) - l0;

    float pos = v[0], neg = 0.f, ok = 1.f;
    #pragma unroll
    for (int j = 1; j < 17; j++) {
        neg += v[j];
        if (v[j] < v[0]) ok = 0.f;
    }

    sl[t] = loss; sp[t] = pos; sn[t] = neg; sa[t] = ok;
    __syncthreads();
    for (int st = 128; st > 0; st >>= 1) {
        if (t < st) {
            sl[t] += sl[t + st]; sp[t] += sp[t + st];
            sn[t] += sn[t + st]; sa[t] += sa[t + st];
        }
        __syncthreads();
    }
    if (t == 0) {
        g_part[blockIdx.x][0] = sl[0];
        g_part[blockIdx.x][1] = sp[0];
        g_part[blockIdx.x][2] = sn[0];
        g_part[blockIdx.x][3] = sa[0];
    }
}

__global__ void reduce2(float* __restrict__ out) {
    __shared__ float s[128][4];
    const int t = threadIdx.x;
    #pragma unroll
    for (int c = 0; c < 4; c++) s[t][c] = g_part[t][c];
    __syncthreads();
    for (int st = 64; st > 0; st >>= 1) {
        if (t < st) {
            #pragma unroll
            for (int c = 0; c < 4; c++) s[t][c] += s[t + st][c];
        }
        __syncthreads();
    }
    if (t == 0) {
        out[0] = s[0][0] / 32768.0f;
        out[1] = s[0][1] / 32768.0f;
        out[2] = s[0][2] / (32768.0f * 16.0f);
        out[3] = s[0][3] / 32768.0f;
    }
}

// ---------------------------------------------------------------------------
extern "C" void kernel_launch(void* const* d_in, const int* in_sizes, int n_in,
                              void* d_out, int out_size) {
    const float* anchor    = (const float*)d_in[0];
    const float* positive  = (const float*)d_in[1];
    const float* negatives = (const float*)d_in[2];
    const float* W1 = (const float*)d_in[3];
    const float* b1 = (const float*)d_in[4];
    const float* W2 = (const float*)d_in[5];
    const float* b2 = (const float*)d_in[6];
    const float* W3 = (const float*)d_in[7];
    const float* b3 = (const float*)d_in[8];
    const float* W4 = (const float*)d_in[9];
    const float* b4 = (const float*)d_in[10];
    float* out = (float*)d_out;

    cudaFuncSetAttribute(mmaA,    cudaFuncAttributeMaxDynamicSharedMemorySize, SMEM_EN);
    cudaFuncSetAttribute(energyT, cudaFuncAttributeMaxDynamicSharedMemorySize, SMEM_EN);

    prepW_a<<<512, 256>>>(W1);                                      // 1 (zeros g_cnt)
    prepW_b<<<160, 256>>>(W2, W3);                                  // 2
    mmaA<<<NB / 128, 256, SMEM_EN>>>(anchor, b1);                   // 3
    energyT<<<NBLK, 256, SMEM_EN>>>(positive, negatives, b2, b3, W4, b4); // 4 (profiled)
    flagK<<<NB / 256, 256>>>();                                     // 5
    fixup2<<<FIXGRID, 128>>>(anchor, positive, negatives,
                             W1, b1, W2, b2, W3, b3, W4, b4);       // 6
    reduce1<<<128, 256>>>();                                        // 7
    reduce2<<<1, 128>>>(out);                                       // 8
}